// round 16
// baseline (speedup 1.0000x reference)
#include <cuda_runtime.h>
#include <cuda_fp16.h>
#include <mma.h>
#include <cstdint>

using namespace nvcuda;

#define NN 100000
#define EE 1600000
#define DD 128

// Scratch (__device__ globals; zero-initialized at module load).
__device__ __half d_gh[(size_t)(NN + 128) * DD];   // g in fp16 (scatter messages)
__device__ float  d_dinv[NN];
__device__ int    d_deg[NN];                       // starts 0; reset to 0 each call
__device__ __half d_WcTh[DD * DD];                 // WcT[k][c], fp16

// ---------------------------------------------------------------------------
// 1) count in-degrees; 4 edges per thread (deg starts at 0 each call)
__global__ void count_deg_kernel(const int* __restrict__ ei, int E) {
    int t = blockIdx.x * blockDim.x + threadIdx.x;
    int e = t * 4;
    if (e + 4 <= E) {
        int4 c = __ldg((const int4*)&ei[E + e]);
        atomicAdd(&d_deg[c.x], 1);
        atomicAdd(&d_deg[c.y], 1);
        atomicAdd(&d_deg[c.z], 1);
        atomicAdd(&d_deg[c.w], 1);
    } else {
        for (; e < E; e++) atomicAdd(&d_deg[__ldg(&ei[E + e])], 1);
    }
}

// 2) fused: dinv = rsqrt(deg + 1) with deg reset to 0 (restores replay invariant)
//    + WcTh[k][c] = fp16(sum_m Wg[c][m]*Wl[m][k])
__global__ void dinv_combine_kernel(const float* __restrict__ Wl,
                                    const float* __restrict__ Wg, int n) {
    if (blockIdx.x < DD) {
        int k = blockIdx.x;
        int c = threadIdx.x;
        float s0 = 0.f, s1 = 0.f, s2 = 0.f, s3 = 0.f;
#pragma unroll 8
        for (int m = 0; m < DD; m += 4) {
            s0 += __ldg(&Wg[c * DD + m + 0]) * __ldg(&Wl[(m + 0) * DD + k]);
            s1 += __ldg(&Wg[c * DD + m + 1]) * __ldg(&Wl[(m + 1) * DD + k]);
            s2 += __ldg(&Wg[c * DD + m + 2]) * __ldg(&Wl[(m + 2) * DD + k]);
            s3 += __ldg(&Wg[c * DD + m + 3]) * __ldg(&Wl[(m + 3) * DD + k]);
        }
        d_WcTh[k * DD + c] = __float2half_rn((s0 + s1) + (s2 + s3));
    } else {
        int i = (blockIdx.x - DD) * blockDim.x + threadIdx.x;
        if (i < n) {
            int d = d_deg[i];
            d_deg[i] = 0;                       // restore zero for next call
            d_dinv[i] = rsqrtf((float)(d + 1)); // +1 = self loop
        }
    }
}

// 3) fp16 wmma GEMM, smem-staged epilogue, grid-stride persistent CTAs.
//    g = (dinv*x) @ WcT  (fp16 in, fp32 accum) -> smem stage ->
//    d_gh = fp16(g);  out = dinv*g + b
#define XS_LD 136                          // halves
#define STG_LD 132                         // floats
#define SMEM_BYTES (2 * 128 * XS_LD * 2)   // 69632 >= 128*STG_LD*4 = 67584

__global__ __launch_bounds__(256, 2) void gemm_g_kernel(const float* __restrict__ x,
                                                        const float* __restrict__ bias,
                                                        float* __restrict__ out,
                                                        int n, int nblk) {
    extern __shared__ char smraw[];
    __half* xs = (__half*)smraw;               // [128][XS_LD]
    __half* ws = xs + 128 * XS_LD;             // [128][XS_LD]
    float*  stage = (float*)smraw;             // [128][STG_LD] (reused after MMAs)

    const int tid = threadIdx.x;
    const int warp = tid >> 5;
    const int wrow = (warp >> 1) * 32;
    const int wcol = (warp & 1) * 64;

    const float4* x4 = (const float4*)x;
    const uint4* w16 = (const uint4*)d_WcTh;
    const float4* bias4 = (const float4*)bias;
    float4* o4 = (float4*)out;
    uint2* gh2 = (uint2*)d_gh;

    for (int b0 = blockIdx.x; b0 < nblk; b0 += gridDim.x) {
        const int row0 = b0 * 128;

        // Load A: fp16(dinv * x)
#pragma unroll
        for (int i = 0; i < 16; i++) {
            int idx = tid + 256 * i;
            int r = idx >> 5;
            int c4 = idx & 31;
            int grow = row0 + r;
            float4 v = make_float4(0.f, 0.f, 0.f, 0.f);
            float di = 0.f;
            if (grow < n) {
                di = d_dinv[grow];
                v = __ldg(&x4[grow * 32 + c4]);
            }
            __half2 h0 = __floats2half2_rn(v.x * di, v.y * di);
            __half2 h1 = __floats2half2_rn(v.z * di, v.w * di);
            uint2 p;
            p.x = *reinterpret_cast<unsigned*>(&h0);
            p.y = *reinterpret_cast<unsigned*>(&h1);
            *(uint2*)&xs[r * XS_LD + c4 * 4] = p;
        }
        // Load B: WcTh
#pragma unroll
        for (int i = 0; i < 8; i++) {
            int idx = tid + 256 * i;
            int k = idx >> 4;
            int c8 = idx & 15;
            uint4 v = __ldg(&w16[k * 16 + c8]);
            *(uint4*)&ws[k * XS_LD + c8 * 8] = v;
        }
        __syncthreads();

        wmma::fragment<wmma::accumulator, 16, 16, 16, float> acc[2][4];
#pragma unroll
        for (int i = 0; i < 2; i++)
#pragma unroll
            for (int j = 0; j < 4; j++) wmma::fill_fragment(acc[i][j], 0.0f);

#pragma unroll
        for (int ks = 0; ks < 8; ks++) {
            wmma::fragment<wmma::matrix_a, 16, 16, 16, __half, wmma::row_major> a[2];
            wmma::load_matrix_sync(a[0], &xs[wrow * XS_LD + ks * 16], XS_LD);
            wmma::load_matrix_sync(a[1], &xs[(wrow + 16) * XS_LD + ks * 16], XS_LD);
#pragma unroll
            for (int j = 0; j < 4; j++) {
                wmma::fragment<wmma::matrix_b, 16, 16, 16, __half, wmma::row_major> b;
                wmma::load_matrix_sync(b, &ws[(ks * 16) * XS_LD + wcol + j * 16], XS_LD);
                wmma::mma_sync(acc[0][j], a[0], b, acc[0][j]);
                wmma::mma_sync(acc[1][j], a[1], b, acc[1][j]);
            }
        }
        __syncthreads();   // A/B smem dead; reuse as fp32 stage

#pragma unroll
        for (int i = 0; i < 2; i++)
#pragma unroll
            for (int j = 0; j < 4; j++) {
                wmma::store_matrix_sync(&stage[(wrow + i * 16) * STG_LD + wcol + j * 16],
                                        acc[i][j], STG_LD, wmma::mem_row_major);
            }
        __syncthreads();

        // Epilogue from stage: d_gh (fp16) + out = dinv*g + b
#pragma unroll
        for (int i = 0; i < 16; i++) {
            int idx = tid + 256 * i;           // 0..4095
            int r = idx >> 5;
            int c4 = idx & 31;
            int grow = row0 + r;
            if (grow < n) {
                float4 g = *(float4*)&stage[r * STG_LD + c4 * 4];
                __half2 h0 = __floats2half2_rn(g.x, g.y);
                __half2 h1 = __floats2half2_rn(g.z, g.w);
                uint2 p;
                p.x = *reinterpret_cast<unsigned*>(&h0);
                p.y = *reinterpret_cast<unsigned*>(&h1);
                gh2[grow * 32 + c4] = p;
                float di = d_dinv[grow];
                float4 bb = __ldg(&bias4[c4]);
                float4 o;
                o.x = di * g.x + bb.x;
                o.y = di * g.y + bb.y;
                o.z = di * g.z + bb.z;
                o.w = di * g.w + bb.w;
                o4[grow * 32 + c4] = o;
            }
        }
        __syncthreads();   // stage reads done before next iteration overwrites xs
    }
}

// 4) scatter: 32 edges per warp, lane-parallel index staging + shfl broadcast.
//    Index/dinv loads: coalesced per-lane (3 instr for 32 edges) instead of
//    96 uniform loads. gh reads fp16 (256B/row), fp32 v4 RED accumulation.
__global__ void scatter_kernel(const int* __restrict__ ei,
                               float* __restrict__ out, int E) {
    int warp = (blockIdx.x * blockDim.x + threadIdx.x) >> 5;
    int lane = threadIdx.x & 31;
    int base = warp * 32;
    if (base >= E) return;

    const uint2* gh2 = (const uint2*)d_gh;
    float4* o4 = (float4*)out;

    // Lane-parallel staging: lane l owns edge base+l.
    int r = 0, c = 0;
    float dc = 0.f;
    if (base + lane < E) {
        r = __ldg(&ei[base + lane]);
        c = __ldg(&ei[E + base + lane]);
        dc = __ldg(&d_dinv[c]);
    }

    auto do_edge = [&](int t) {
        int rt = __shfl_sync(0xffffffffu, r, t);
        int ct = __shfl_sync(0xffffffffu, c, t);
        float dct = __shfl_sync(0xffffffffu, dc, t);
        uint2 raw = __ldg(&gh2[rt * 32 + lane]);
        __half2 h0 = *reinterpret_cast<__half2*>(&raw.x);
        __half2 h1 = *reinterpret_cast<__half2*>(&raw.y);
        float2 f0 = __half22float2(h0);
        float2 f1 = __half22float2(h1);
        float4 v;
        v.x = f0.x * dct; v.y = f0.y * dct; v.z = f1.x * dct; v.w = f1.y * dct;
        float4* addr = &o4[ct * 32 + lane];
        asm volatile("red.global.add.v4.f32 [%0], {%1,%2,%3,%4};"
                     :: "l"(addr), "f"(v.x), "f"(v.y), "f"(v.z), "f"(v.w)
                     : "memory");
    };

    int cnt = min(32, E - base);
    if (cnt == 32) {
#pragma unroll 8
        for (int t = 0; t < 32; t++) do_edge(t);
    } else {
        for (int t = 0; t < cnt; t++) do_edge(t);
    }
}

extern "C" void kernel_launch(void* const* d_in, const int* in_sizes, int n_in,
                              void* d_out, int out_size) {
    const float* x  = (const float*)d_in[0];
    const int*   ei = (const int*)d_in[1];     // int32 on device
    const float* Wl = (const float*)d_in[2];
    const float* Wg = (const float*)d_in[3];
    const float* b  = (const float*)d_in[4];
    float* out = (float*)d_out;

    int n = in_sizes[0] / DD;     // 100000
    int E = in_sizes[1] / 2;      // 1600000

    int qthreads = (E + 3) / 4;
    count_deg_kernel<<<(qthreads + 255) / 256, 256>>>(ei, E);
    dinv_combine_kernel<<<DD + (n + 127) / 128, 128>>>(Wl, Wg, n);

    int nblk = (n + 127) / 128;
    int gblocks = nblk < 296 ? nblk : 296;    // 2 CTAs/SM * 148 SMs
    cudaFuncSetAttribute(gemm_g_kernel, cudaFuncAttributeMaxDynamicSharedMemorySize,
                         SMEM_BYTES);
    gemm_g_kernel<<<gblocks, 256, SMEM_BYTES>>>(x, b, out, n, nblk);

    int warps = (E + 31) / 32;
    int sblocks = (warps * 32 + 255) / 256;
    scatter_kernel<<<sblocks, 256>>>(ei, out, E);
}

// round 17
// speedup vs baseline: 1.0572x; 1.0572x over previous
#include <cuda_runtime.h>
#include <cuda_fp16.h>
#include <mma.h>
#include <cstdint>

using namespace nvcuda;

#define NN 100000
#define EE 1600000
#define DD 128

// Scratch (__device__ globals; zero-initialized at module load).
__device__ __half d_gh[(size_t)(NN + 128) * DD];   // g in fp16 (scatter messages)
__device__ float  d_dinv[NN];
__device__ int    d_deg[NN];                       // starts 0; reset to 0 each call
__device__ __half d_WcTh[DD * DD];                 // WcT[k][c], fp16

// ---------------------------------------------------------------------------
// 1) count in-degrees; 4 edges per thread (deg starts at 0 each call)
__global__ void count_deg_kernel(const int* __restrict__ ei, int E) {
    int t = blockIdx.x * blockDim.x + threadIdx.x;
    int e = t * 4;
    if (e + 4 <= E) {
        int4 c = __ldg((const int4*)&ei[E + e]);
        atomicAdd(&d_deg[c.x], 1);
        atomicAdd(&d_deg[c.y], 1);
        atomicAdd(&d_deg[c.z], 1);
        atomicAdd(&d_deg[c.w], 1);
    } else {
        for (; e < E; e++) atomicAdd(&d_deg[__ldg(&ei[E + e])], 1);
    }
}

// 2) fused: dinv = rsqrt(deg + 1) with deg reset to 0 (restores replay invariant)
//    + WcTh[k][c] = fp16(sum_m Wg[c][m]*Wl[m][k])
__global__ void dinv_combine_kernel(const float* __restrict__ Wl,
                                    const float* __restrict__ Wg, int n) {
    if (blockIdx.x < DD) {
        int k = blockIdx.x;
        int c = threadIdx.x;
        float s0 = 0.f, s1 = 0.f, s2 = 0.f, s3 = 0.f;
#pragma unroll 8
        for (int m = 0; m < DD; m += 4) {
            s0 += __ldg(&Wg[c * DD + m + 0]) * __ldg(&Wl[(m + 0) * DD + k]);
            s1 += __ldg(&Wg[c * DD + m + 1]) * __ldg(&Wl[(m + 1) * DD + k]);
            s2 += __ldg(&Wg[c * DD + m + 2]) * __ldg(&Wl[(m + 2) * DD + k]);
            s3 += __ldg(&Wg[c * DD + m + 3]) * __ldg(&Wl[(m + 3) * DD + k]);
        }
        d_WcTh[k * DD + c] = __float2half_rn((s0 + s1) + (s2 + s3));
    } else {
        int i = (blockIdx.x - DD) * blockDim.x + threadIdx.x;
        if (i < n) {
            int d = d_deg[i];
            d_deg[i] = 0;                       // restore zero for next call
            d_dinv[i] = rsqrtf((float)(d + 1)); // +1 = self loop
        }
    }
}

// 3) fp16 wmma GEMM, smem-staged epilogue, grid-stride persistent CTAs.
//    g = (dinv*x) @ WcT  (fp16 in, fp32 accum) -> smem stage ->
//    d_gh = fp16(g);  out = dinv*g + b
#define XS_LD 136                          // halves
#define STG_LD 132                         // floats
#define SMEM_BYTES (2 * 128 * XS_LD * 2)   // 69632 >= 128*STG_LD*4 = 67584

__global__ __launch_bounds__(256, 2) void gemm_g_kernel(const float* __restrict__ x,
                                                        const float* __restrict__ bias,
                                                        float* __restrict__ out,
                                                        int n, int nblk) {
    extern __shared__ char smraw[];
    __half* xs = (__half*)smraw;               // [128][XS_LD]
    __half* ws = xs + 128 * XS_LD;             // [128][XS_LD]
    float*  stage = (float*)smraw;             // [128][STG_LD] (reused after MMAs)

    const int tid = threadIdx.x;
    const int warp = tid >> 5;
    const int wrow = (warp >> 1) * 32;
    const int wcol = (warp & 1) * 64;

    const float4* x4 = (const float4*)x;
    const uint4* w16 = (const uint4*)d_WcTh;
    const float4* bias4 = (const float4*)bias;
    float4* o4 = (float4*)out;
    uint2* gh2 = (uint2*)d_gh;

    for (int b0 = blockIdx.x; b0 < nblk; b0 += gridDim.x) {
        const int row0 = b0 * 128;

        // Load A: fp16(dinv * x)
#pragma unroll
        for (int i = 0; i < 16; i++) {
            int idx = tid + 256 * i;
            int r = idx >> 5;
            int c4 = idx & 31;
            int grow = row0 + r;
            float4 v = make_float4(0.f, 0.f, 0.f, 0.f);
            float di = 0.f;
            if (grow < n) {
                di = d_dinv[grow];
                v = __ldg(&x4[grow * 32 + c4]);
            }
            __half2 h0 = __floats2half2_rn(v.x * di, v.y * di);
            __half2 h1 = __floats2half2_rn(v.z * di, v.w * di);
            uint2 p;
            p.x = *reinterpret_cast<unsigned*>(&h0);
            p.y = *reinterpret_cast<unsigned*>(&h1);
            *(uint2*)&xs[r * XS_LD + c4 * 4] = p;
        }
        // Load B: WcTh
#pragma unroll
        for (int i = 0; i < 8; i++) {
            int idx = tid + 256 * i;
            int k = idx >> 4;
            int c8 = idx & 15;
            uint4 v = __ldg(&w16[k * 16 + c8]);
            *(uint4*)&ws[k * XS_LD + c8 * 8] = v;
        }
        __syncthreads();

        wmma::fragment<wmma::accumulator, 16, 16, 16, float> acc[2][4];
#pragma unroll
        for (int i = 0; i < 2; i++)
#pragma unroll
            for (int j = 0; j < 4; j++) wmma::fill_fragment(acc[i][j], 0.0f);

#pragma unroll
        for (int ks = 0; ks < 8; ks++) {
            wmma::fragment<wmma::matrix_a, 16, 16, 16, __half, wmma::row_major> a[2];
            wmma::load_matrix_sync(a[0], &xs[wrow * XS_LD + ks * 16], XS_LD);
            wmma::load_matrix_sync(a[1], &xs[(wrow + 16) * XS_LD + ks * 16], XS_LD);
#pragma unroll
            for (int j = 0; j < 4; j++) {
                wmma::fragment<wmma::matrix_b, 16, 16, 16, __half, wmma::row_major> b;
                wmma::load_matrix_sync(b, &ws[(ks * 16) * XS_LD + wcol + j * 16], XS_LD);
                wmma::mma_sync(acc[0][j], a[0], b, acc[0][j]);
                wmma::mma_sync(acc[1][j], a[1], b, acc[1][j]);
            }
        }
        __syncthreads();   // A/B smem dead; reuse as fp32 stage

#pragma unroll
        for (int i = 0; i < 2; i++)
#pragma unroll
            for (int j = 0; j < 4; j++) {
                wmma::store_matrix_sync(&stage[(wrow + i * 16) * STG_LD + wcol + j * 16],
                                        acc[i][j], STG_LD, wmma::mem_row_major);
            }
        __syncthreads();

        // Epilogue from stage: d_gh (fp16) + out = dinv*g + b
#pragma unroll
        for (int i = 0; i < 16; i++) {
            int idx = tid + 256 * i;           // 0..4095
            int r = idx >> 5;
            int c4 = idx & 31;
            int grow = row0 + r;
            if (grow < n) {
                float4 g = *(float4*)&stage[r * STG_LD + c4 * 4];
                __half2 h0 = __floats2half2_rn(g.x, g.y);
                __half2 h1 = __floats2half2_rn(g.z, g.w);
                uint2 p;
                p.x = *reinterpret_cast<unsigned*>(&h0);
                p.y = *reinterpret_cast<unsigned*>(&h1);
                gh2[grow * 32 + c4] = p;
                float di = d_dinv[grow];
                float4 bb = __ldg(&bias4[c4]);
                float4 o;
                o.x = di * g.x + bb.x;
                o.y = di * g.y + bb.y;
                o.z = di * g.z + bb.z;
                o.w = di * g.w + bb.w;
                o4[grow * 32 + c4] = o;
            }
        }
        __syncthreads();   // stage reads done before next iteration overwrites xs
    }
}

// 4) scatter: flat random edge order, 8 edges per warp (R15-proven structure),
//    int4-batched warp-uniform index loads (4 instr per 8 edges instead of 16).
//    fp16 message reads, fp32 v4 RED accumulation.
#define EPW 8
__global__ void scatter_kernel(const int* __restrict__ ei,
                               float* __restrict__ out, int E) {
    int warp = (blockIdx.x * blockDim.x + threadIdx.x) >> 5;
    int lane = threadIdx.x & 31;
    const uint2* gh2 = (const uint2*)d_gh;
    float4* o4 = (float4*)out;
    int base = warp * EPW;

    auto do_edge = [&](int r, int c) {
        float dc = __ldg(&d_dinv[c]);
        uint2 raw = __ldg(&gh2[r * 32 + lane]);
        __half2 h0 = *reinterpret_cast<__half2*>(&raw.x);
        __half2 h1 = *reinterpret_cast<__half2*>(&raw.y);
        float2 f0 = __half22float2(h0);
        float2 f1 = __half22float2(h1);
        float4 v;
        v.x = f0.x * dc; v.y = f0.y * dc; v.z = f1.x * dc; v.w = f1.y * dc;
        float4* addr = &o4[c * 32 + lane];
        asm volatile("red.global.add.v4.f32 [%0], {%1,%2,%3,%4};"
                     :: "l"(addr), "f"(v.x), "f"(v.y), "f"(v.z), "f"(v.w)
                     : "memory");
    };

    if (base + EPW <= E) {
        // E % 4 == 0 and base % 8 == 0: int4 loads are in-bounds & aligned
        const int4* r4 = (const int4*)&ei[base];
        const int4* c4p = (const int4*)&ei[E + base];
        int4 r03 = __ldg(&r4[0]);
        int4 r47 = __ldg(&r4[1]);
        int4 c03 = __ldg(&c4p[0]);
        int4 c47 = __ldg(&c4p[1]);
        do_edge(r03.x, c03.x);
        do_edge(r03.y, c03.y);
        do_edge(r03.z, c03.z);
        do_edge(r03.w, c03.w);
        do_edge(r47.x, c47.x);
        do_edge(r47.y, c47.y);
        do_edge(r47.z, c47.z);
        do_edge(r47.w, c47.w);
    } else {
        for (int e = base; e < E; e++) {
            int r = __ldg(&ei[e]);
            int c = __ldg(&ei[E + e]);
            do_edge(r, c);
        }
    }
}

extern "C" void kernel_launch(void* const* d_in, const int* in_sizes, int n_in,
                              void* d_out, int out_size) {
    const float* x  = (const float*)d_in[0];
    const int*   ei = (const int*)d_in[1];     // int32 on device
    const float* Wl = (const float*)d_in[2];
    const float* Wg = (const float*)d_in[3];
    const float* b  = (const float*)d_in[4];
    float* out = (float*)d_out;

    int n = in_sizes[0] / DD;     // 100000
    int E = in_sizes[1] / 2;      // 1600000

    int qthreads = (E + 3) / 4;
    count_deg_kernel<<<(qthreads + 255) / 256, 256>>>(ei, E);
    dinv_combine_kernel<<<DD + (n + 127) / 128, 128>>>(Wl, Wg, n);

    int nblk = (n + 127) / 128;
    int gblocks = nblk < 296 ? nblk : 296;    // 2 CTAs/SM * 148 SMs
    cudaFuncSetAttribute(gemm_g_kernel, cudaFuncAttributeMaxDynamicSharedMemorySize,
                         SMEM_BYTES);
    gemm_g_kernel<<<gblocks, 256, SMEM_BYTES>>>(x, b, out, n, nblk);

    int warps = (E + EPW - 1) / EPW;
    int sblocks = (warps * 32 + 255) / 256;
    scatter_kernel<<<sblocks, 256>>>(ei, out, E);
}